// round 8
// baseline (speedup 1.0000x reference)
#include <cuda_runtime.h>
#include <math.h>

#define NB 64
#define NS 257
#define ND 768
#define NH 12
#define HD 64
#define NTOK (NB*NS)          /* 16448 */
#define NQKV (NTOK*ND)        /* 12632064 */
#define NBH (NB*NH)           /* 768 */
#define EPSV 1e-10f
#define LAMDA 0.475f

// ---------------- device scratch ----------------
__device__ float g_qkv[3*NQKV];            // q | k | v, each (B,H,S,HD)
__device__ float g_ctx[NQKV];              // (B,S,D)
__device__ float g_ent[NBH*NS];            // entropy row, [0]=1
__device__ float g_loss1[NBH];
__device__ float g_loss2[NBH];
__device__ float g_part1[(size_t)NBH*256*8];  // p1 layer-2 partial dots
__device__ float g_part2[(size_t)NBH*64*8];   // p2 layer-2 partial dots

// ---------------- tf32 helpers ----------------
__device__ __forceinline__ unsigned f2tf32(float x){
    unsigned r; asm("cvt.rna.tf32.f32 %0, %1;" : "=r"(r) : "f"(x)); return r;
}
__device__ __forceinline__ void mma_tf32(float* c,
    unsigned a0, unsigned a1, unsigned a2, unsigned a3,
    unsigned b0, unsigned b1)
{
    asm volatile(
      "mma.sync.aligned.m16n8k8.row.col.f32.tf32.tf32.f32 "
      "{%0,%1,%2,%3},{%4,%5,%6,%7},{%8,%9},{%0,%1,%2,%3};"
      : "+f"(c[0]), "+f"(c[1]), "+f"(c[2]), "+f"(c[3])
      : "r"(a0), "r"(a1), "r"(a2), "r"(a3), "r"(b0), "r"(b1));
}

// =====================================================================
// Tensor-core tf32 GEMM: BM=128, BN=128, BK=16, 256 threads, smem 2-stage.
// AMODE 0: A row-major [M,K] (guarded)
// AMODE 2: p1 feature gather (row m -> bh,t in k tensor), lda=64
// AMODE 3: p2 merged-patch gather (K=256 -> q,d decomposition)
// EMODE 0: C row-major + bias
// EMODE 1: qkv scatter (B,H,S,HD) + bias
// EMODE 3: fused relu + dot with W2 -> per-(row, col-slice) partials in C
// =====================================================================
template<int AMODE, int EMODE>
__global__ void __launch_bounds__(256)
gemm_tc(const float* __restrict__ A, const float* __restrict__ W,
        const float* __restrict__ bias, const float* __restrict__ W2,
        float* __restrict__ C, int M, int N, int K)
{
    __shared__ unsigned As[2][16][132];
    __shared__ unsigned Bs[2][16][132];

    const int tid  = threadIdx.x;
    const int lane = tid & 31;
    const int warp = tid >> 5;
    const int g    = lane >> 2;
    const int t4   = lane & 3;
    const int wm   = (warp & 3) * 32;
    const int wn   = (warp >> 2) * 64;
    const int mBase = blockIdx.y * 128;
    const int nBase = blockIdx.x * 128;

    const int aRow = tid >> 1;
    const int aK   = (tid & 1) * 8;
    const int bRow = tid >> 4;
    const int bCol = (tid & 15) * 8;

    long aOff = -1;
    int  rowbase = 0, pr2 = 0, pc2 = 0;
    if (AMODE == 0) {
        int m = mBase + aRow;
        if (m < M) aOff = (long)m * K;
    } else if (AMODE == 2) {
        int m  = mBase + aRow;
        int bh = m >> 8, t = m & 255;
        aOff = ((long)bh * NS + 1 + t) * HD;
    } else { // AMODE 3
        int m  = mBase + aRow;
        int bh = m >> 6, patch = m & 63;
        rowbase = bh * NS + 1;
        pr2 = patch >> 3; pc2 = patch & 7;
    }

    float ra[8], rb[8];

    auto loadAB = [&](int k0) {
        if (AMODE == 3) {
            int kk = k0 + aK;
            int q = kk >> 6, d = kk & 63;
            int token = (2*pr2 + (q >> 1)) * 16 + 2*pc2 + (q & 1);
            const float4* p = (const float4*)(A + ((long)(rowbase + token)) * HD + d);
            float4 v0 = p[0], v1 = p[1];
            ra[0]=v0.x; ra[1]=v0.y; ra[2]=v0.z; ra[3]=v0.w;
            ra[4]=v1.x; ra[5]=v1.y; ra[6]=v1.z; ra[7]=v1.w;
        } else {
            if (aOff >= 0) {
                const float4* p = (const float4*)(A + aOff + k0 + aK);
                float4 v0 = p[0], v1 = p[1];
                ra[0]=v0.x; ra[1]=v0.y; ra[2]=v0.z; ra[3]=v0.w;
                ra[4]=v1.x; ra[5]=v1.y; ra[6]=v1.z; ra[7]=v1.w;
            } else {
                #pragma unroll
                for (int j = 0; j < 8; ++j) ra[j] = 0.f;
            }
        }
        const float4* p = (const float4*)(W + (long)(k0 + bRow) * N + nBase + bCol);
        float4 v0 = p[0], v1 = p[1];
        rb[0]=v0.x; rb[1]=v0.y; rb[2]=v0.z; rb[3]=v0.w;
        rb[4]=v1.x; rb[5]=v1.y; rb[6]=v1.z; rb[7]=v1.w;
    };
    auto stageAB = [&](int buf) {
        #pragma unroll
        for (int j = 0; j < 8; ++j) As[buf][aK + j][aRow] = f2tf32(ra[j]);
        #pragma unroll
        for (int j = 0; j < 8; ++j) Bs[buf][bRow][bCol + j] = f2tf32(rb[j]);
    };

    float acc[2][8][4];
    #pragma unroll
    for (int mt = 0; mt < 2; ++mt)
        #pragma unroll
        for (int nt = 0; nt < 8; ++nt)
            #pragma unroll
            for (int i = 0; i < 4; ++i) acc[mt][nt][i] = 0.f;

    loadAB(0);
    stageAB(0);
    __syncthreads();
    int cur = 0;

    for (int k0 = 0; k0 < K; k0 += 16) {
        const bool more = (k0 + 16) < K;
        if (more) loadAB(k0 + 16);

        #pragma unroll
        for (int ks = 0; ks < 2; ++ks) {
            const int kr = ks * 8;
            unsigned af[2][4];
            #pragma unroll
            for (int mt = 0; mt < 2; ++mt) {
                int m0 = wm + mt * 16;
                af[mt][0] = As[cur][kr + t4    ][m0 + g    ];
                af[mt][1] = As[cur][kr + t4    ][m0 + g + 8];
                af[mt][2] = As[cur][kr + t4 + 4][m0 + g    ];
                af[mt][3] = As[cur][kr + t4 + 4][m0 + g + 8];
            }
            #pragma unroll
            for (int nt = 0; nt < 8; ++nt) {
                int n0 = wn + nt * 8 + g;
                unsigned b0 = Bs[cur][kr + t4    ][n0];
                unsigned b1 = Bs[cur][kr + t4 + 4][n0];
                mma_tf32(acc[0][nt], af[0][0], af[0][1], af[0][2], af[0][3], b0, b1);
                mma_tf32(acc[1][nt], af[1][0], af[1][1], af[1][2], af[1][3], b0, b1);
            }
        }
        if (more) {
            stageAB(cur ^ 1);
            __syncthreads();
            cur ^= 1;
        }
    }

    // ---- epilogue
    if (EMODE == 3) {
        // fused relu + dot(W2) partials. part[mt][half] = row partial over
        // this warp's 64-column slice.
        float part[2][2] = {{0.f, 0.f}, {0.f, 0.f}};
        #pragma unroll
        for (int nt = 0; nt < 8; ++nt) {
            int c0 = nBase + wn + nt * 8 + 2 * t4;
            float bi0 = __ldg(bias + c0),  bi1 = __ldg(bias + c0 + 1);
            float w20 = __ldg(W2 + c0),    w21 = __ldg(W2 + c0 + 1);
            #pragma unroll
            for (int mt = 0; mt < 2; ++mt) {
                part[mt][0] = fmaf(fmaxf(acc[mt][nt][0] + bi0, 0.f), w20, part[mt][0]);
                part[mt][0] = fmaf(fmaxf(acc[mt][nt][1] + bi1, 0.f), w21, part[mt][0]);
                part[mt][1] = fmaf(fmaxf(acc[mt][nt][2] + bi0, 0.f), w20, part[mt][1]);
                part[mt][1] = fmaf(fmaxf(acc[mt][nt][3] + bi1, 0.f), w21, part[mt][1]);
            }
        }
        #pragma unroll
        for (int mt = 0; mt < 2; ++mt)
            #pragma unroll
            for (int hf = 0; hf < 2; ++hf) {
                float v = part[mt][hf];
                v += __shfl_xor_sync(0xffffffffu, v, 1);
                v += __shfl_xor_sync(0xffffffffu, v, 2);
                part[mt][hf] = v;
            }
        if (t4 == 0) {
            #pragma unroll
            for (int mt = 0; mt < 2; ++mt)
                #pragma unroll
                for (int hf = 0; hf < 2; ++hf) {
                    long m = mBase + wm + mt * 16 + g + hf * 8;
                    C[m * 8 + blockIdx.x * 2 + (warp >> 2)] = part[mt][hf];
                }
        }
    } else {
        #pragma unroll
        for (int mt = 0; mt < 2; ++mt) {
            int r0 = mBase + wm + mt * 16 + g;
            #pragma unroll
            for (int nt = 0; nt < 8; ++nt) {
                int c0 = nBase + wn + nt * 8 + 2 * t4;
                #pragma unroll
                for (int half = 0; half < 2; ++half) {
                    int m = r0 + half * 8;
                    float v0 = acc[mt][nt][half*2 + 0];
                    float v1 = acc[mt][nt][half*2 + 1];
                    if (EMODE == 0) {
                        if (m < M) {
                            float* cp = C + (long)m * N + c0;
                            cp[0] = v0 + bias[c0];
                            cp[1] = v1 + bias[c0 + 1];
                        }
                    } else { // EMODE 1: qkv scatter
                        if (m < M) {
                            int b = m / NS, s = m % NS;
                            int hh0 = c0 >> 6, hd0 = c0 & 63;
                            float* cp = g_qkv + ((((long)b * NH + hh0) * NS + s) * HD + hd0);
                            long ofs = (long)(C - g_qkv);
                            cp += ofs;
                            cp[0] = v0 + bias[c0];
                            cp[1] = v1 + bias[c0 + 1];
                        }
                    }
                }
            }
        }
    }
}

// =====================================================================
// adv_finish: per (b,h): p2 (64), p1 (256), entropy, per-bh losses.
// =====================================================================
__global__ void adv_finish(const float* __restrict__ a2, const float* __restrict__ b2)
{
    __shared__ float sm_p2[64];
    __shared__ float sred1[8], sred2[8];
    const int bh = blockIdx.x;
    const int tid = threadIdx.x, lane = tid & 31, w = tid >> 5;

    // p2: threads 0..63
    float l2 = 0.f;
    if (tid < 64) {
        const float* pp = g_part2 + ((size_t)bh * 64 + tid) * 8;
        float s = b2[0];
        #pragma unroll
        for (int i = 0; i < 8; ++i) s += pp[i];
        float p = 1.f / (1.f + expf(-s));
        sm_p2[tid] = p;
        l2 = logf(fmaxf(1.f - p, EPSV));
    }
    // p1: every thread one token
    float l1;
    float p1v;
    {
        const float* pp = g_part1 + ((size_t)bh * 256 + tid) * 8;
        float s = a2[0];
        #pragma unroll
        for (int i = 0; i < 8; ++i) s += pp[i];
        p1v = 1.f / (1.f + expf(-s));
        l1 = logf(fmaxf(1.f - p1v, EPSV));
    }
    // warp reduce
    #pragma unroll
    for (int o = 16; o > 0; o >>= 1) {
        l1 += __shfl_xor_sync(0xffffffffu, l1, o);
        l2 += __shfl_xor_sync(0xffffffffu, l2, o);
    }
    if (lane == 0) { sred1[w] = l1; sred2[w] = l2; }
    __syncthreads();

    // entropy
    {
        int t = tid;
        int gr = t >> 4, gc = t & 15;
        int m  = (gr >> 1) * 8 + (gc >> 1);
        float ad  = (1.f - LAMDA) * p1v + LAMDA * sm_p2[m];
        float ent = -ad * log2f(ad + EPSV) - (1.f - ad) * log2f(1.f - ad + EPSV);
        g_ent[bh * NS + 1 + t] = ent;
    }
    if (tid == 0) {
        g_ent[bh * NS] = 1.f;
        float s1 = 0.f, s2 = 0.f;
        #pragma unroll
        for (int i = 0; i < 8; ++i) { s1 += sred1[i]; s2 += sred2[i]; }
        g_loss1[bh] = s1;
        g_loss2[bh] = s2;
    }
}

// =====================================================================
// Attention: one block per (b,h), 512 threads (16 warps).
// =====================================================================
__global__ void __launch_bounds__(512)
attn_kernel()
{
    extern __shared__ float sm[];
    float* sm_kT = sm;                    // [64][257]
    float* sm_v  = sm + 64*NS;            // [257][64]
    float* sm_p  = sm_v + NS*64;          // [16][257]

    const int bh   = blockIdx.x;
    const int tid  = threadIdx.x;
    const int lane = tid & 31;
    const int w    = tid >> 5;

    const float* qb = g_qkv + (size_t)bh * NS * HD;
    const float* kb = g_qkv + (size_t)NQKV + (size_t)bh * NS * HD;
    const float* vb = g_qkv + (size_t)2*NQKV + (size_t)bh * NS * HD;

    for (int i = tid; i < NS*64; i += 512) {
        int t = i >> 6, d = i & 63;
        sm_kT[d*NS + t] = kb[i];
        sm_v[i]         = vb[i];
    }
    __syncthreads();

    const int b = bh / NH, h = bh % NH;

    for (int s = w; s < NS; s += 16) {
        float q[64];
        #pragma unroll
        for (int d = 0; d < 64; ++d) q[d] = qb[s*64 + d];

        float sc[9];
        #pragma unroll
        for (int c = 0; c < 9; ++c) {
            int kt = lane + 32*c;
            float acc = -1e30f;
            if (kt < NS) {
                acc = 0.f;
                #pragma unroll
                for (int d = 0; d < 64; ++d)
                    acc = fmaf(q[d], sm_kT[d*NS + kt], acc);
                acc *= 0.125f;
            }
            sc[c] = acc;
        }
        float mx = sc[0];
        #pragma unroll
        for (int c = 1; c < 9; ++c) mx = fmaxf(mx, sc[c]);
        #pragma unroll
        for (int o = 16; o > 0; o >>= 1) mx = fmaxf(mx, __shfl_xor_sync(0xffffffffu, mx, o));

        float sum = 0.f;
        #pragma unroll
        for (int c = 0; c < 9; ++c) {
            int kt = lane + 32*c;
            float e = (kt < NS) ? expf(sc[c] - mx) : 0.f;
            sc[c] = e;
            sum += e;
        }
        #pragma unroll
        for (int o = 16; o > 0; o >>= 1) sum += __shfl_xor_sync(0xffffffffu, sum, o);
        float inv = 1.f / sum;

        __syncwarp();
        #pragma unroll
        for (int c = 0; c < 9; ++c) {
            int kt = lane + 32*c;
            if (kt < NS) {
                float p = sc[c] * inv;
                if (s == 0) p *= g_ent[bh*NS + kt];
                sm_p[w*NS + kt] = p;
            }
        }
        __syncwarp();

        float acc0 = 0.f, acc1 = 0.f;
        const float* pw = sm_p + w*NS;
        #pragma unroll 4
        for (int kt = 0; kt < 256; ++kt) {
            float pv = pw[kt];
            acc0 = fmaf(pv, sm_v[kt*64 + lane],      acc0);
            acc1 = fmaf(pv, sm_v[kt*64 + 32 + lane], acc1);
        }
        {
            float pv = pw[256];
            acc0 = fmaf(pv, sm_v[256*64 + lane],      acc0);
            acc1 = fmaf(pv, sm_v[256*64 + 32 + lane], acc1);
        }
        float* cp = g_ctx + ((size_t)(b*NS + s)) * ND + h*HD;
        cp[lane]      = acc0;
        cp[32 + lane] = acc1;
        __syncwarp();
    }
}

// =====================================================================
// Final deterministic loss reduction
// =====================================================================
__global__ void loss_kernel(float* __restrict__ out)
{
    __shared__ float s1[256], s2[256];
    int tid = threadIdx.x;
    float a = 0.f, b = 0.f;
    for (int i = tid; i < NBH; i += 256) { a += g_loss1[i]; b += g_loss2[i]; }
    s1[tid] = a; s2[tid] = b;
    __syncthreads();
    for (int o = 128; o > 0; o >>= 1) {
        if (tid < o) { s1[tid] += s1[tid + o]; s2[tid] += s2[tid + o]; }
        __syncthreads();
    }
    if (tid == 0)
        out[0] = -s1[0] / ((float)NBH * 256.f) - s2[0] / ((float)NBH * 64.f);
}

// =====================================================================
// Launch
// =====================================================================
extern "C" void kernel_launch(void* const* d_in, const int* in_sizes, int n_in,
                              void* d_out, int out_size)
{
    const float* X  = (const float*)d_in[0];
    const float* Wq = (const float*)d_in[1];
    const float* bq = (const float*)d_in[2];
    const float* Wk = (const float*)d_in[3];
    const float* bk = (const float*)d_in[4];
    const float* Wv = (const float*)d_in[5];
    const float* bv = (const float*)d_in[6];
    const float* Wo = (const float*)d_in[7];
    const float* bo = (const float*)d_in[8];
    const float* A1 = (const float*)d_in[9];
    const float* a1 = (const float*)d_in[10];
    const float* A2 = (const float*)d_in[11];
    const float* a2 = (const float*)d_in[12];
    const float* B1 = (const float*)d_in[13];
    const float* b1 = (const float*)d_in[14];
    const float* B2 = (const float*)d_in[15];
    const float* b2 = (const float*)d_in[16];
    float* out = (float*)d_out;

    float *qkv = nullptr, *ctx = nullptr, *pt1 = nullptr, *pt2 = nullptr;
    cudaGetSymbolAddress((void**)&qkv, g_qkv);
    cudaGetSymbolAddress((void**)&ctx, g_ctx);
    cudaGetSymbolAddress((void**)&pt1, g_part1);
    cudaGetSymbolAddress((void**)&pt2, g_part2);
    float* kbase = qkv + NQKV;

    const int ATTN_SMEM = (64*NS + NS*64 + 16*NS) * 4;   // 148032 B
    cudaFuncSetAttribute(attn_kernel, cudaFuncAttributeMaxDynamicSharedMemorySize, ATTN_SMEM);

    dim3 gproj(ND/128, (NTOK + 127)/128);   // (6, 129)

    gemm_tc<0,1><<<gproj, 256>>>(X, Wq, bq, nullptr, qkv,           NTOK, ND, ND);
    gemm_tc<0,1><<<gproj, 256>>>(X, Wk, bk, nullptr, qkv + NQKV,    NTOK, ND, ND);
    gemm_tc<0,1><<<gproj, 256>>>(X, Wv, bv, nullptr, qkv + 2*NQKV,  NTOK, ND, ND);

    // adversarial layer-1 GEMMs with fused relu+layer-2 partial dot
    gemm_tc<2,3><<<dim3(4, (NBH*256)/128), 256>>>(kbase, A1, a1, A2, pt1, NBH*256, 512, 64);
    gemm_tc<3,3><<<dim3(4, (NBH*64)/128),  256>>>(kbase, B1, b1, B2, pt2, NBH*64,  512, 256);

    adv_finish<<<NBH, 256>>>(a2, b2);

    attn_kernel<<<NBH, 512, ATTN_SMEM>>>();

    gemm_tc<0,0><<<gproj, 256>>>(ctx, Wo, bo, nullptr, out, NTOK, ND, ND);

    if (out_size > NQKV)
        loss_kernel<<<1, 256>>>(out + (out_size - 1));
}

// round 9
// speedup vs baseline: 1.5468x; 1.5468x over previous
#include <cuda_runtime.h>
#include <math.h>

#define NB 64
#define NS 257
#define ND 768
#define NH 12
#define HD 64
#define NTOK (NB*NS)          /* 16448 */
#define NQKV (NTOK*ND)        /* 12632064 */
#define NBH (NB*NH)           /* 768 */
#define EPSV 1e-10f
#define LAMDA 0.475f

// ---------------- device scratch ----------------
__device__ float g_qkv[3*NQKV];            // q | k | v, each (B,H,S,HD)
__device__ float g_ctx[NQKV];              // (B,S,D)
__device__ float g_ent[NBH*NS];            // entropy row, [0]=1
__device__ float g_loss1[NBH];
__device__ float g_loss2[NBH];
__device__ float g_part1[(size_t)NBH*256*8];  // p1 layer-2 partial dots
__device__ float g_part2[(size_t)NBH*64*8];   // p2 layer-2 partial dots

// ---------------- tf32 helpers ----------------
__device__ __forceinline__ unsigned f2tf32(float x){
    unsigned r; asm("cvt.rna.tf32.f32 %0, %1;" : "=r"(r) : "f"(x)); return r;
}
__device__ __forceinline__ void mma_tf32(float* c,
    unsigned a0, unsigned a1, unsigned a2, unsigned a3,
    unsigned b0, unsigned b1)
{
    asm volatile(
      "mma.sync.aligned.m16n8k8.row.col.f32.tf32.tf32.f32 "
      "{%0,%1,%2,%3},{%4,%5,%6,%7},{%8,%9},{%0,%1,%2,%3};"
      : "+f"(c[0]), "+f"(c[1]), "+f"(c[2]), "+f"(c[3])
      : "r"(a0), "r"(a1), "r"(a2), "r"(a3), "r"(b0), "r"(b1));
}

// =====================================================================
// Tensor-core tf32 GEMM: BM=128, BN=128, BK=16, 256 threads, smem 2-stage.
// AMODE 0: A row-major [M,K] (guarded)
// AMODE 2: p1 feature gather (row m -> bh,t in k tensor), lda=64
// AMODE 3: p2 merged-patch gather (K=256 -> q,d decomposition)
// EMODE 0: C row-major + bias
// EMODE 1: qkv scatter (B,H,S,HD) + bias
// EMODE 3: fused relu + dot with W2 -> per-(row, col-slice) partials in C
// =====================================================================
template<int AMODE, int EMODE>
__global__ void __launch_bounds__(256)
gemm_tc(const float* __restrict__ A, const float* __restrict__ W,
        const float* __restrict__ bias, const float* __restrict__ W2,
        float* __restrict__ C, int M, int N, int K)
{
    __shared__ unsigned As[2][16][132];
    __shared__ unsigned Bs[2][16][132];

    const int tid  = threadIdx.x;
    const int lane = tid & 31;
    const int warp = tid >> 5;
    const int g    = lane >> 2;
    const int t4   = lane & 3;
    const int wm   = (warp & 3) * 32;
    const int wn   = (warp >> 2) * 64;
    const int mBase = blockIdx.y * 128;
    const int nBase = blockIdx.x * 128;

    const int aRow = tid >> 1;
    const int aK   = (tid & 1) * 8;
    const int bRow = tid >> 4;
    const int bCol = (tid & 15) * 8;

    long aOff = -1;
    int  rowbase = 0, pr2 = 0, pc2 = 0;
    if (AMODE == 0) {
        int m = mBase + aRow;
        if (m < M) aOff = (long)m * K;
    } else if (AMODE == 2) {
        int m  = mBase + aRow;
        int bh = m >> 8, t = m & 255;
        aOff = ((long)bh * NS + 1 + t) * HD;
    } else { // AMODE 3
        int m  = mBase + aRow;
        int bh = m >> 6, patch = m & 63;
        rowbase = bh * NS + 1;
        pr2 = patch >> 3; pc2 = patch & 7;
    }

    float ra[8], rb[8];

    auto loadAB = [&](int k0) {
        if (AMODE == 3) {
            int kk = k0 + aK;
            int q = kk >> 6, d = kk & 63;
            int token = (2*pr2 + (q >> 1)) * 16 + 2*pc2 + (q & 1);
            const float4* p = (const float4*)(A + ((long)(rowbase + token)) * HD + d);
            float4 v0 = p[0], v1 = p[1];
            ra[0]=v0.x; ra[1]=v0.y; ra[2]=v0.z; ra[3]=v0.w;
            ra[4]=v1.x; ra[5]=v1.y; ra[6]=v1.z; ra[7]=v1.w;
        } else {
            if (aOff >= 0) {
                const float4* p = (const float4*)(A + aOff + k0 + aK);
                float4 v0 = p[0], v1 = p[1];
                ra[0]=v0.x; ra[1]=v0.y; ra[2]=v0.z; ra[3]=v0.w;
                ra[4]=v1.x; ra[5]=v1.y; ra[6]=v1.z; ra[7]=v1.w;
            } else {
                #pragma unroll
                for (int j = 0; j < 8; ++j) ra[j] = 0.f;
            }
        }
        const float4* p = (const float4*)(W + (long)(k0 + bRow) * N + nBase + bCol);
        float4 v0 = p[0], v1 = p[1];
        rb[0]=v0.x; rb[1]=v0.y; rb[2]=v0.z; rb[3]=v0.w;
        rb[4]=v1.x; rb[5]=v1.y; rb[6]=v1.z; rb[7]=v1.w;
    };
    auto stageAB = [&](int buf) {
        #pragma unroll
        for (int j = 0; j < 8; ++j) As[buf][aK + j][aRow] = f2tf32(ra[j]);
        #pragma unroll
        for (int j = 0; j < 8; ++j) Bs[buf][bRow][bCol + j] = f2tf32(rb[j]);
    };

    float acc[2][8][4];
    #pragma unroll
    for (int mt = 0; mt < 2; ++mt)
        #pragma unroll
        for (int nt = 0; nt < 8; ++nt)
            #pragma unroll
            for (int i = 0; i < 4; ++i) acc[mt][nt][i] = 0.f;

    loadAB(0);
    stageAB(0);
    __syncthreads();
    int cur = 0;

    for (int k0 = 0; k0 < K; k0 += 16) {
        const bool more = (k0 + 16) < K;
        if (more) loadAB(k0 + 16);

        #pragma unroll
        for (int ks = 0; ks < 2; ++ks) {
            const int kr = ks * 8;
            unsigned af[2][4];
            #pragma unroll
            for (int mt = 0; mt < 2; ++mt) {
                int m0 = wm + mt * 16;
                af[mt][0] = As[cur][kr + t4    ][m0 + g    ];
                af[mt][1] = As[cur][kr + t4    ][m0 + g + 8];
                af[mt][2] = As[cur][kr + t4 + 4][m0 + g    ];
                af[mt][3] = As[cur][kr + t4 + 4][m0 + g + 8];
            }
            #pragma unroll
            for (int nt = 0; nt < 8; ++nt) {
                int n0 = wn + nt * 8 + g;
                unsigned b0 = Bs[cur][kr + t4    ][n0];
                unsigned b1 = Bs[cur][kr + t4 + 4][n0];
                mma_tf32(acc[0][nt], af[0][0], af[0][1], af[0][2], af[0][3], b0, b1);
                mma_tf32(acc[1][nt], af[1][0], af[1][1], af[1][2], af[1][3], b0, b1);
            }
        }
        if (more) {
            stageAB(cur ^ 1);
            __syncthreads();
            cur ^= 1;
        }
    }

    // ---- epilogue
    if (EMODE == 3) {
        float part[2][2] = {{0.f, 0.f}, {0.f, 0.f}};
        #pragma unroll
        for (int nt = 0; nt < 8; ++nt) {
            int c0 = nBase + wn + nt * 8 + 2 * t4;
            float bi0 = __ldg(bias + c0),  bi1 = __ldg(bias + c0 + 1);
            float w20 = __ldg(W2 + c0),    w21 = __ldg(W2 + c0 + 1);
            #pragma unroll
            for (int mt = 0; mt < 2; ++mt) {
                part[mt][0] = fmaf(fmaxf(acc[mt][nt][0] + bi0, 0.f), w20, part[mt][0]);
                part[mt][0] = fmaf(fmaxf(acc[mt][nt][1] + bi1, 0.f), w21, part[mt][0]);
                part[mt][1] = fmaf(fmaxf(acc[mt][nt][2] + bi0, 0.f), w20, part[mt][1]);
                part[mt][1] = fmaf(fmaxf(acc[mt][nt][3] + bi1, 0.f), w21, part[mt][1]);
            }
        }
        #pragma unroll
        for (int mt = 0; mt < 2; ++mt)
            #pragma unroll
            for (int hf = 0; hf < 2; ++hf) {
                float v = part[mt][hf];
                v += __shfl_xor_sync(0xffffffffu, v, 1);
                v += __shfl_xor_sync(0xffffffffu, v, 2);
                part[mt][hf] = v;
            }
        if (t4 == 0) {
            #pragma unroll
            for (int mt = 0; mt < 2; ++mt)
                #pragma unroll
                for (int hf = 0; hf < 2; ++hf) {
                    long m = mBase + wm + mt * 16 + g + hf * 8;
                    C[m * 8 + blockIdx.x * 2 + (warp >> 2)] = part[mt][hf];
                }
        }
    } else {
        #pragma unroll
        for (int mt = 0; mt < 2; ++mt) {
            int r0 = mBase + wm + mt * 16 + g;
            #pragma unroll
            for (int nt = 0; nt < 8; ++nt) {
                int c0 = nBase + wn + nt * 8 + 2 * t4;
                #pragma unroll
                for (int half = 0; half < 2; ++half) {
                    int m = r0 + half * 8;
                    float v0 = acc[mt][nt][half*2 + 0];
                    float v1 = acc[mt][nt][half*2 + 1];
                    if (EMODE == 0) {
                        if (m < M) {
                            float* cp = C + (long)m * N + c0;
                            cp[0] = v0 + bias[c0];
                            cp[1] = v1 + bias[c0 + 1];
                        }
                    } else { // EMODE 1: qkv scatter
                        if (m < M) {
                            int b = m / NS, s = m % NS;
                            int hh0 = c0 >> 6, hd0 = c0 & 63;
                            float* cp = g_qkv + ((((long)b * NH + hh0) * NS + s) * HD + hd0);
                            long ofs = (long)(C - g_qkv);
                            cp += ofs;
                            cp[0] = v0 + bias[c0];
                            cp[1] = v1 + bias[c0 + 1];
                        }
                    }
                }
            }
        }
    }
}

// =====================================================================
// adv_finish: per (b,h): p2 (64), p1 (256), entropy, per-bh losses.
// =====================================================================
__global__ void adv_finish(const float* __restrict__ a2, const float* __restrict__ b2)
{
    __shared__ float sm_p2[64];
    __shared__ float sred1[8], sred2[8];
    const int bh = blockIdx.x;
    const int tid = threadIdx.x, lane = tid & 31, w = tid >> 5;

    float l2 = 0.f;
    if (tid < 64) {
        const float* pp = g_part2 + ((size_t)bh * 64 + tid) * 8;
        float s = b2[0];
        #pragma unroll
        for (int i = 0; i < 8; ++i) s += pp[i];
        float p = 1.f / (1.f + expf(-s));
        sm_p2[tid] = p;
        l2 = logf(fmaxf(1.f - p, EPSV));
    }
    float l1;
    float p1v;
    {
        const float* pp = g_part1 + ((size_t)bh * 256 + tid) * 8;
        float s = a2[0];
        #pragma unroll
        for (int i = 0; i < 8; ++i) s += pp[i];
        p1v = 1.f / (1.f + expf(-s));
        l1 = logf(fmaxf(1.f - p1v, EPSV));
    }
    #pragma unroll
    for (int o = 16; o > 0; o >>= 1) {
        l1 += __shfl_xor_sync(0xffffffffu, l1, o);
        l2 += __shfl_xor_sync(0xffffffffu, l2, o);
    }
    if (lane == 0) { sred1[w] = l1; sred2[w] = l2; }
    __syncthreads();

    {
        int t = tid;
        int gr = t >> 4, gc = t & 15;
        int m  = (gr >> 1) * 8 + (gc >> 1);
        float ad  = (1.f - LAMDA) * p1v + LAMDA * sm_p2[m];
        float ent = -ad * log2f(ad + EPSV) - (1.f - ad) * log2f(1.f - ad + EPSV);
        g_ent[bh * NS + 1 + t] = ent;
    }
    if (tid == 0) {
        g_ent[bh * NS] = 1.f;
        float s1 = 0.f, s2 = 0.f;
        #pragma unroll
        for (int i = 0; i < 8; ++i) { s1 += sred1[i]; s2 += sred2[i]; }
        g_loss1[bh] = s1;
        g_loss2[bh] = s2;
    }
}

// =====================================================================
// Tensor-core attention: one block per (b,h), 256 threads (8 warps).
// K (tf32) [264][68] and V^T (tf32) [64][268] staged in smem.
// Warp w handles 16-query m-tiles {2w, 2w+1}; softmax in MMA fragments;
// P C-frag -> A-frag via in-quad shfl transpose; ctx = P @ V^T via MMA.
// Query 256 handled scalar by warp 7.
// =====================================================================
#define KS_STRIDE 68
#define VT_STRIDE 268

__global__ void __launch_bounds__(256, 1)
attn_kernel()
{
    extern __shared__ unsigned smu[];
    unsigned* Ksm   = smu;                        // 264*68
    unsigned* VTu   = smu + 264*KS_STRIDE;        // 64*268
    float*    entS  = (float*)(VTu + 64*VT_STRIDE); // 264
    float*    sP    = entS + 264;                 // 264 (warp-7 scalar path)

    const int bh   = blockIdx.x;
    const int tid  = threadIdx.x;
    const int lane = tid & 31;
    const int w    = tid >> 5;
    const int g    = lane >> 2;
    const int t4   = lane & 3;

    const float* qb = g_qkv + (size_t)bh * NS * HD;
    const float* kb = g_qkv + (size_t)NQKV + (size_t)bh * NS * HD;
    const float* vb = g_qkv + (size_t)2*NQKV + (size_t)bh * NS * HD;

    // ---- stage K (tf32) and V^T (tf32), zero padding, ent row
    for (int i = tid; i < NS*64; i += 256) {
        int t = i >> 6, d = i & 63;
        Ksm[t*KS_STRIDE + d] = f2tf32(kb[i]);
        VTu[d*VT_STRIDE + t] = f2tf32(vb[i]);
    }
    for (int i = tid; i < 7*64; i += 256) {       // K rows 257..263 = 0
        int t = 257 + (i >> 6), d = i & 63;
        Ksm[t*KS_STRIDE + d] = 0u;
    }
    for (int i = tid; i < 64*8; i += 256) {       // VT cols 257..263 = 0
        int d = i >> 3, c = 256 + (i & 7);
        if (c >= 257) VTu[d*VT_STRIDE + c] = 0u;
    }
    for (int i = tid; i < 264; i += 256)
        entS[i] = (i < NS) ? g_ent[bh*NS + i] : 0.f;
    __syncthreads();

    const int b = bh / NH, h = bh % NH;
    const int qbase = lane & ~3;   // 4g: base lane of this quad

    #pragma unroll
    for (int ti = 0; ti < 2; ++ti) {
        const int tile = w*2 + ti;
        const int m0   = tile * 16;

        // ---- Q fragments (registers, loaded once)
        unsigned aq[8][4];
        const float* q0 = qb + (m0 + g) * 64;
        const float* q1 = qb + (m0 + g + 8) * 64;
        #pragma unroll
        for (int ks = 0; ks < 8; ++ks) {
            aq[ks][0] = f2tf32(q0[ks*8 + t4]);
            aq[ks][1] = f2tf32(q1[ks*8 + t4]);
            aq[ks][2] = f2tf32(q0[ks*8 + t4 + 4]);
            aq[ks][3] = f2tf32(q1[ks*8 + t4 + 4]);
        }

        // ---- S = Q @ K^T  (33 n-tiles over 264 tokens)
        float sf[33][4];
        #pragma unroll
        for (int nt = 0; nt < 33; ++nt) {
            float c4[4] = {0.f, 0.f, 0.f, 0.f};
            const unsigned* kr = Ksm + (nt*8 + g) * KS_STRIDE;
            #pragma unroll
            for (int ks = 0; ks < 8; ++ks)
                mma_tf32(c4, aq[ks][0], aq[ks][1], aq[ks][2], aq[ks][3],
                         kr[ks*8 + t4], kr[ks*8 + t4 + 4]);
            sf[nt][0] = c4[0] * 0.125f;
            sf[nt][1] = c4[1] * 0.125f;
            sf[nt][2] = c4[2] * 0.125f;
            sf[nt][3] = c4[3] * 0.125f;
        }

        // ---- softmax in fragments (rows g and g+8)
        float mx0 = -1e30f, mx1 = -1e30f;
        #pragma unroll
        for (int nt = 0; nt < 32; ++nt) {
            mx0 = fmaxf(mx0, fmaxf(sf[nt][0], sf[nt][1]));
            mx1 = fmaxf(mx1, fmaxf(sf[nt][2], sf[nt][3]));
        }
        if (t4 == 0) {                 // tile 32: only col 256 valid
            mx0 = fmaxf(mx0, sf[32][0]);
            mx1 = fmaxf(mx1, sf[32][2]);
        }
        mx0 = fmaxf(mx0, __shfl_xor_sync(0xffffffffu, mx0, 1));
        mx0 = fmaxf(mx0, __shfl_xor_sync(0xffffffffu, mx0, 2));
        mx1 = fmaxf(mx1, __shfl_xor_sync(0xffffffffu, mx1, 1));
        mx1 = fmaxf(mx1, __shfl_xor_sync(0xffffffffu, mx1, 2));

        float sum0 = 0.f, sum1 = 0.f;
        #pragma unroll
        for (int nt = 0; nt < 32; ++nt) {
            sf[nt][0] = expf(sf[nt][0] - mx0); sum0 += sf[nt][0];
            sf[nt][1] = expf(sf[nt][1] - mx0); sum0 += sf[nt][1];
            sf[nt][2] = expf(sf[nt][2] - mx1); sum1 += sf[nt][2];
            sf[nt][3] = expf(sf[nt][3] - mx1); sum1 += sf[nt][3];
        }
        {
            float e0 = (t4 == 0) ? expf(sf[32][0] - mx0) : 0.f;
            float e2 = (t4 == 0) ? expf(sf[32][2] - mx1) : 0.f;
            sf[32][0] = e0; sum0 += e0;
            sf[32][1] = 0.f;
            sf[32][2] = e2; sum1 += e2;
            sf[32][3] = 0.f;
        }
        sum0 += __shfl_xor_sync(0xffffffffu, sum0, 1);
        sum0 += __shfl_xor_sync(0xffffffffu, sum0, 2);
        sum1 += __shfl_xor_sync(0xffffffffu, sum1, 1);
        sum1 += __shfl_xor_sync(0xffffffffu, sum1, 2);
        const float inv0 = 1.f / sum0, inv1 = 1.f / sum1;

        const bool entRow = (tile == 0) && (g == 0);
        #pragma unroll
        for (int nt = 0; nt < 33; ++nt) {
            sf[nt][0] *= inv0;
            sf[nt][1] *= inv0;
            sf[nt][2] *= inv1;
            sf[nt][3] *= inv1;
            if (entRow) {
                sf[nt][0] *= entS[nt*8 + 2*t4];
                sf[nt][1] *= entS[nt*8 + 2*t4 + 1];
            }
        }

        // ---- ctx = P @ V^T  (33 k-steps, 8 n-tiles over d=64)
        float oc[8][4];
        #pragma unroll
        for (int nt = 0; nt < 8; ++nt)
            #pragma unroll
            for (int i = 0; i < 4; ++i) oc[nt][i] = 0.f;

        const int l1 = qbase + (t4 >> 1);
        const int l2 = l1 + 2;
        const bool odd = (t4 & 1);

        #pragma unroll
        for (int ks = 0; ks < 33; ++ks) {
            unsigned u0 = f2tf32(sf[ks][0]);
            unsigned u1 = f2tf32(sf[ks][1]);
            unsigned u2 = f2tf32(sf[ks][2]);
            unsigned u3 = f2tf32(sf[ks][3]);
            unsigned x0a = __shfl_sync(0xffffffffu, u0, l1);
            unsigned x0b = __shfl_sync(0xffffffffu, u1, l1);
            unsigned x1a = __shfl_sync(0xffffffffu, u2, l1);
            unsigned x1b = __shfl_sync(0xffffffffu, u3, l1);
            unsigned y0a = __shfl_sync(0xffffffffu, u0, l2);
            unsigned y0b = __shfl_sync(0xffffffffu, u1, l2);
            unsigned y1a = __shfl_sync(0xffffffffu, u2, l2);
            unsigned y1b = __shfl_sync(0xffffffffu, u3, l2);
            unsigned a0 = odd ? x0b : x0a;
            unsigned a1 = odd ? x1b : x1a;
            unsigned a2 = odd ? y0b : y0a;
            unsigned a3 = odd ? y1b : y1a;
            #pragma unroll
            for (int nt = 0; nt < 8; ++nt) {
                const unsigned* vr = VTu + (nt*8 + g) * VT_STRIDE + ks*8;
                mma_tf32(oc[nt], a0, a1, a2, a3, vr[t4], vr[t4 + 4]);
            }
        }

        // ---- write ctx rows (all < 256)
        float* base0 = g_ctx + ((size_t)(b*NS + m0 + g    )) * ND + h*HD;
        float* base1 = g_ctx + ((size_t)(b*NS + m0 + g + 8)) * ND + h*HD;
        #pragma unroll
        for (int nt = 0; nt < 8; ++nt) {
            int c0 = nt*8 + 2*t4;
            base0[c0]     = oc[nt][0];
            base0[c0 + 1] = oc[nt][1];
            base1[c0]     = oc[nt][2];
            base1[c0 + 1] = oc[nt][3];
        }
    }

    // ---- query 256: scalar path on warp 7
    if (w == 7) {
        float q[64];
        #pragma unroll
        for (int d = 0; d < 64; ++d) q[d] = qb[256*64 + d];

        float sc[9];
        #pragma unroll
        for (int c = 0; c < 9; ++c) {
            int kt = lane + 32*c;
            float acc = -1e30f;
            if (kt <= 256) {
                acc = 0.f;
                const unsigned* kr = Ksm + kt * KS_STRIDE;
                #pragma unroll
                for (int d = 0; d < 64; ++d)
                    acc = fmaf(q[d], __uint_as_float(kr[d]), acc);
                acc *= 0.125f;
            }
            sc[c] = acc;
        }
        float mx = sc[0];
        #pragma unroll
        for (int c = 1; c < 9; ++c) mx = fmaxf(mx, sc[c]);
        #pragma unroll
        for (int o = 16; o > 0; o >>= 1) mx = fmaxf(mx, __shfl_xor_sync(0xffffffffu, mx, o));
        float sum = 0.f;
        #pragma unroll
        for (int c = 0; c < 9; ++c) {
            int kt = lane + 32*c;
            float e = (kt <= 256) ? expf(sc[c] - mx) : 0.f;
            sc[c] = e; sum += e;
        }
        #pragma unroll
        for (int o = 16; o > 0; o >>= 1) sum += __shfl_xor_sync(0xffffffffu, sum, o);
        float inv = 1.f / sum;
        #pragma unroll
        for (int c = 0; c < 9; ++c) {
            int kt = lane + 32*c;
            if (kt <= 256) sP[kt] = sc[c] * inv;
        }
        __syncwarp();

        float a0 = 0.f, a1 = 0.f;
        const unsigned* v0 = VTu + (size_t)lane * VT_STRIDE;
        const unsigned* v1 = VTu + (size_t)(lane + 32) * VT_STRIDE;
        for (int t = 0; t < NS; ++t) {
            float pv = sP[t];
            a0 = fmaf(pv, __uint_as_float(v0[t]), a0);
            a1 = fmaf(pv, __uint_as_float(v1[t]), a1);
        }
        float* cp = g_ctx + ((size_t)(b*NS + 256)) * ND + h*HD;
        cp[lane]      = a0;
        cp[lane + 32] = a1;
    }
}

// =====================================================================
// Final deterministic loss reduction
// =====================================================================
__global__ void loss_kernel(float* __restrict__ out)
{
    __shared__ float s1[256], s2[256];
    int tid = threadIdx.x;
    float a = 0.f, b = 0.f;
    for (int i = tid; i < NBH; i += 256) { a += g_loss1[i]; b += g_loss2[i]; }
    s1[tid] = a; s2[tid] = b;
    __syncthreads();
    for (int o = 128; o > 0; o >>= 1) {
        if (tid < o) { s1[tid] += s1[tid + o]; s2[tid] += s2[tid + o]; }
        __syncthreads();
    }
    if (tid == 0)
        out[0] = -s1[0] / ((float)NBH * 256.f) - s2[0] / ((float)NBH * 64.f);
}

// =====================================================================
// Launch
// =====================================================================
extern "C" void kernel_launch(void* const* d_in, const int* in_sizes, int n_in,
                              void* d_out, int out_size)
{
    const float* X  = (const float*)d_in[0];
    const float* Wq = (const float*)d_in[1];
    const float* bq = (const float*)d_in[2];
    const float* Wk = (const float*)d_in[3];
    const float* bk = (const float*)d_in[4];
    const float* Wv = (const float*)d_in[5];
    const float* bv = (const float*)d_in[6];
    const float* Wo = (const float*)d_in[7];
    const float* bo = (const float*)d_in[8];
    const float* A1 = (const float*)d_in[9];
    const float* a1 = (const float*)d_in[10];
    const float* A2 = (const float*)d_in[11];
    const float* a2 = (const float*)d_in[12];
    const float* B1 = (const float*)d_in[13];
    const float* b1 = (const float*)d_in[14];
    const float* B2 = (const float*)d_in[15];
    const float* b2 = (const float*)d_in[16];
    float* out = (float*)d_out;

    float *qkv = nullptr, *ctx = nullptr, *pt1 = nullptr, *pt2 = nullptr;
    cudaGetSymbolAddress((void**)&qkv, g_qkv);
    cudaGetSymbolAddress((void**)&ctx, g_ctx);
    cudaGetSymbolAddress((void**)&pt1, g_part1);
    cudaGetSymbolAddress((void**)&pt2, g_part2);
    float* kbase = qkv + NQKV;

    const int ATTN_SMEM = (264*KS_STRIDE + 64*VT_STRIDE + 264 + 264) * 4; // 142528
    cudaFuncSetAttribute(attn_kernel, cudaFuncAttributeMaxDynamicSharedMemorySize, ATTN_SMEM);

    dim3 gproj(ND/128, (NTOK + 127)/128);   // (6, 129)

    gemm_tc<0,1><<<gproj, 256>>>(X, Wq, bq, nullptr, qkv,           NTOK, ND, ND);
    gemm_tc<0,1><<<gproj, 256>>>(X, Wk, bk, nullptr, qkv + NQKV,    NTOK, ND, ND);
    gemm_tc<0,1><<<gproj, 256>>>(X, Wv, bv, nullptr, qkv + 2*NQKV,  NTOK, ND, ND);

    gemm_tc<2,3><<<dim3(4, (NBH*256)/128), 256>>>(kbase, A1, a1, A2, pt1, NBH*256, 512, 64);
    gemm_tc<3,3><<<dim3(4, (NBH*64)/128),  256>>>(kbase, B1, b1, B2, pt2, NBH*64,  512, 256);

    adv_finish<<<NBH, 256>>>(a2, b2);

    attn_kernel<<<NBH, 256, ATTN_SMEM>>>();

    gemm_tc<0,0><<<gproj, 256>>>(ctx, Wo, bo, nullptr, out, NTOK, ND, ND);

    if (out_size > NQKV)
        loss_kernel<<<1, 256>>>(out + (out_size - 1));
}

// round 10
// speedup vs baseline: 2.0870x; 1.3492x over previous
#include <cuda_runtime.h>
#include <math.h>

#define NB 64
#define NS 257
#define ND 768
#define NH 12
#define HD 64
#define NTOK (NB*NS)          /* 16448 */
#define NQKV (NTOK*ND)        /* 12632064 */
#define NBH (NB*NH)           /* 768 */
#define EPSV 1e-10f
#define LAMDA 0.475f

// smem layout strides (uint2 units): kg-stride 132, kh-stride 536, buf 1072
#define KG_STR 132
#define KH_STR 536
#define BUF_STR 1072

// ---------------- device scratch ----------------
__device__ float g_qkv[3*NQKV];            // q | k | v, each (B,H,S,HD)
__device__ float g_ctx[NQKV];              // (B,S,D)
__device__ float g_ent[NBH*NS];            // entropy row, [0]=1
__device__ float g_loss1[NBH];
__device__ float g_loss2[NBH];
__device__ float g_part1[(size_t)NBH*256*8];  // p1 layer-2 partial dots
__device__ float g_part2[(size_t)NBH*64*8];   // p2 layer-2 partial dots

// ---------------- tf32 helpers ----------------
__device__ __forceinline__ unsigned f2tf32(float x){
    unsigned r; asm("cvt.rna.tf32.f32 %0, %1;" : "=r"(r) : "f"(x)); return r;
}
__device__ __forceinline__ void mma_tf32(float* c,
    unsigned a0, unsigned a1, unsigned a2, unsigned a3,
    unsigned b0, unsigned b1)
{
    asm volatile(
      "mma.sync.aligned.m16n8k8.row.col.f32.tf32.tf32.f32 "
      "{%0,%1,%2,%3},{%4,%5,%6,%7},{%8,%9},{%0,%1,%2,%3};"
      : "+f"(c[0]), "+f"(c[1]), "+f"(c[2]), "+f"(c[3])
      : "r"(a0), "r"(a1), "r"(a2), "r"(a3), "r"(b0), "r"(b1));
}

// =====================================================================
// GEMM core macros shared by gemm_tc and gemm_qkv.
// A/B staged as uint2 (k, k+4) pairs for LDS.64 fragment loads.
// =====================================================================

// =====================================================================
// Tensor-core tf32 GEMM: BM=128, BN=128, BK=16, 256 threads, 2-stage smem.
// AMODE 0: A row-major [M,K] (guarded)
// AMODE 2: p1 feature gather (row m -> bh,t in k tensor), lda=64
// AMODE 3: p2 merged-patch gather (K=256 -> q,d decomposition)
// EMODE 0: C row-major + bias
// EMODE 3: fused relu + dot with W2 -> per-(row, col-slice) partials in C
// =====================================================================
template<int AMODE, int EMODE>
__global__ void __launch_bounds__(256)
gemm_tc(const float* __restrict__ A, const float* __restrict__ W,
        const float* __restrict__ bias, const float* __restrict__ W2,
        float* __restrict__ C, int M, int N, int K)
{
    __shared__ uint2 AsI[2*BUF_STR];
    __shared__ uint2 BsI[2*BUF_STR];

    const int tid  = threadIdx.x;
    const int lane = tid & 31;
    const int warp = tid >> 5;
    const int g    = lane >> 2;
    const int t4   = lane & 3;
    const int wm   = (warp & 3) * 32;
    const int wn   = (warp >> 2) * 64;
    const int mBase = blockIdx.y * 128;
    const int nBase = blockIdx.x * 128;

    // A global-load mapping: thread owns row aRow, k-half kh (8 k's)
    const int aRow = tid >> 1;
    const int aKh  = tid & 1;
    // B global-load mapping: warp owns k-slot (kh,kg); lane owns 4 n-cols
    const int bKh  = warp >> 2;
    const int bKg  = warp & 3;
    const int bN   = (tid & 31) * 4;

    long aOff = -1;
    int  rowbase = 0, pr2 = 0, pc2 = 0;
    if (AMODE == 0) {
        int m = mBase + aRow;
        if (m < M) aOff = (long)m * K;
    } else if (AMODE == 2) {
        int m  = mBase + aRow;
        int bh = m >> 8, t = m & 255;
        aOff = ((long)bh * NS + 1 + t) * HD;
    } else { // AMODE 3
        int m  = mBase + aRow;
        int bh = m >> 6, patch = m & 63;
        rowbase = bh * NS + 1;
        pr2 = patch >> 3; pc2 = patch & 7;
    }

    float ra[8], rb[8];

    auto loadAB = [&](int k0) {
        if (AMODE == 3) {
            int kk = k0 + aKh*8;
            int q = kk >> 6, d = kk & 63;
            int token = (2*pr2 + (q >> 1)) * 16 + 2*pc2 + (q & 1);
            const float4* p = (const float4*)(A + ((long)(rowbase + token)) * HD + d);
            float4 v0 = p[0], v1 = p[1];
            ra[0]=v0.x; ra[1]=v0.y; ra[2]=v0.z; ra[3]=v0.w;
            ra[4]=v1.x; ra[5]=v1.y; ra[6]=v1.z; ra[7]=v1.w;
        } else {
            if (aOff >= 0) {
                const float4* p = (const float4*)(A + aOff + k0 + aKh*8);
                float4 v0 = p[0], v1 = p[1];
                ra[0]=v0.x; ra[1]=v0.y; ra[2]=v0.z; ra[3]=v0.w;
                ra[4]=v1.x; ra[5]=v1.y; ra[6]=v1.z; ra[7]=v1.w;
            } else {
                #pragma unroll
                for (int j = 0; j < 8; ++j) ra[j] = 0.f;
            }
        }
        const float4 w0 = *(const float4*)(W + (long)(k0 + bKh*8 + bKg)     * N + nBase + bN);
        const float4 w1 = *(const float4*)(W + (long)(k0 + bKh*8 + bKg + 4) * N + nBase + bN);
        rb[0]=w0.x; rb[1]=w0.y; rb[2]=w0.z; rb[3]=w0.w;
        rb[4]=w1.x; rb[5]=w1.y; rb[6]=w1.z; rb[7]=w1.w;
    };
    auto stageAB = [&](int buf) {
        uint2* Ap = AsI + buf*BUF_STR + aKh*KH_STR + aRow;
        #pragma unroll
        for (int j = 0; j < 4; ++j)
            Ap[j*KG_STR] = make_uint2(f2tf32(ra[j]), f2tf32(ra[j+4]));
        uint2* Bp = BsI + buf*BUF_STR + bKh*KH_STR + bKg*KG_STR + bN;
        #pragma unroll
        for (int j = 0; j < 4; ++j)
            Bp[j] = make_uint2(f2tf32(rb[j]), f2tf32(rb[j+4]));
    };

    float acc[2][8][4];
    #pragma unroll
    for (int mt = 0; mt < 2; ++mt)
        #pragma unroll
        for (int nt = 0; nt < 8; ++nt)
            #pragma unroll
            for (int i = 0; i < 4; ++i) acc[mt][nt][i] = 0.f;

    loadAB(0);
    stageAB(0);
    __syncthreads();
    int cur = 0;

    for (int k0 = 0; k0 < K; k0 += 16) {
        const bool more = (k0 + 16) < K;
        if (more) loadAB(k0 + 16);

        #pragma unroll
        for (int ks = 0; ks < 2; ++ks) {
            const uint2* Ab = AsI + cur*BUF_STR + ks*KH_STR + t4*KG_STR;
            uint2 a00 = Ab[wm + g];
            uint2 a01 = Ab[wm + g + 8];
            uint2 a10 = Ab[wm + 16 + g];
            uint2 a11 = Ab[wm + 16 + g + 8];
            const uint2* Bb = BsI + cur*BUF_STR + ks*KH_STR + t4*KG_STR + wn;
            #pragma unroll
            for (int nt = 0; nt < 8; ++nt) {
                uint2 bb = Bb[nt*8 + g];
                mma_tf32(acc[0][nt], a00.x, a01.x, a00.y, a01.y, bb.x, bb.y);
                mma_tf32(acc[1][nt], a10.x, a11.x, a10.y, a11.y, bb.x, bb.y);
            }
        }
        if (more) {
            stageAB(cur ^ 1);
            __syncthreads();
            cur ^= 1;
        }
    }

    // ---- epilogue
    if (EMODE == 3) {
        float part[2][2] = {{0.f, 0.f}, {0.f, 0.f}};
        #pragma unroll
        for (int nt = 0; nt < 8; ++nt) {
            int c0 = nBase + wn + nt * 8 + 2 * t4;
            float bi0 = __ldg(bias + c0),  bi1 = __ldg(bias + c0 + 1);
            float w20 = __ldg(W2 + c0),    w21 = __ldg(W2 + c0 + 1);
            #pragma unroll
            for (int mt = 0; mt < 2; ++mt) {
                part[mt][0] = fmaf(fmaxf(acc[mt][nt][0] + bi0, 0.f), w20, part[mt][0]);
                part[mt][0] = fmaf(fmaxf(acc[mt][nt][1] + bi1, 0.f), w21, part[mt][0]);
                part[mt][1] = fmaf(fmaxf(acc[mt][nt][2] + bi0, 0.f), w20, part[mt][1]);
                part[mt][1] = fmaf(fmaxf(acc[mt][nt][3] + bi1, 0.f), w21, part[mt][1]);
            }
        }
        #pragma unroll
        for (int mt = 0; mt < 2; ++mt)
            #pragma unroll
            for (int hf = 0; hf < 2; ++hf) {
                float v = part[mt][hf];
                v += __shfl_xor_sync(0xffffffffu, v, 1);
                v += __shfl_xor_sync(0xffffffffu, v, 2);
                part[mt][hf] = v;
            }
        if (t4 == 0) {
            #pragma unroll
            for (int mt = 0; mt < 2; ++mt)
                #pragma unroll
                for (int hf = 0; hf < 2; ++hf) {
                    long m = mBase + wm + mt * 16 + g + hf * 8;
                    C[m * 8 + blockIdx.x * 2 + (warp >> 2)] = part[mt][hf];
                }
        }
    } else { // EMODE 0
        #pragma unroll
        for (int mt = 0; mt < 2; ++mt) {
            int r0 = mBase + wm + mt * 16 + g;
            #pragma unroll
            for (int nt = 0; nt < 8; ++nt) {
                int c0 = nBase + wn + nt * 8 + 2 * t4;
                #pragma unroll
                for (int half = 0; half < 2; ++half) {
                    int m = r0 + half * 8;
                    if (m < M) {
                        float* cp = C + (long)m * N + c0;
                        cp[0] = acc[mt][nt][half*2 + 0] + bias[c0];
                        cp[1] = acc[mt][nt][half*2 + 1] + bias[c0 + 1];
                    }
                }
            }
        }
    }
}

// =====================================================================
// Fused QKV projection: grid (18, 129). blockIdx.x/6 selects Q/K/V.
// Same core as gemm_tc<0,1>, scatter epilogue into g_qkv.
// =====================================================================
__global__ void __launch_bounds__(256)
gemm_qkv(const float* __restrict__ X,
         const float* __restrict__ Wq, const float* __restrict__ bq,
         const float* __restrict__ Wk, const float* __restrict__ bk,
         const float* __restrict__ Wv, const float* __restrict__ bv)
{
    __shared__ uint2 AsI[2*BUF_STR];
    __shared__ uint2 BsI[2*BUF_STR];

    const int which = blockIdx.x / 6;
    const int nblk  = blockIdx.x % 6;
    const float* W    = (which == 0) ? Wq : (which == 1) ? Wk : Wv;
    const float* bias = (which == 0) ? bq : (which == 1) ? bk : bv;
    float* Cout = g_qkv + (size_t)which * NQKV;

    const int tid  = threadIdx.x;
    const int lane = tid & 31;
    const int warp = tid >> 5;
    const int g    = lane >> 2;
    const int t4   = lane & 3;
    const int wm   = (warp & 3) * 32;
    const int wn   = (warp >> 2) * 64;
    const int mBase = blockIdx.y * 128;
    const int nBase = nblk * 128;
    const int Ncol = ND, K = ND;

    const int aRow = tid >> 1;
    const int aKh  = tid & 1;
    const int bKh  = warp >> 2;
    const int bKg  = warp & 3;
    const int bN   = (tid & 31) * 4;

    long aOff = -1;
    {
        int m = mBase + aRow;
        if (m < NTOK) aOff = (long)m * K;
    }

    float ra[8], rb[8];
    auto loadAB = [&](int k0) {
        if (aOff >= 0) {
            const float4* p = (const float4*)(X + aOff + k0 + aKh*8);
            float4 v0 = p[0], v1 = p[1];
            ra[0]=v0.x; ra[1]=v0.y; ra[2]=v0.z; ra[3]=v0.w;
            ra[4]=v1.x; ra[5]=v1.y; ra[6]=v1.z; ra[7]=v1.w;
        } else {
            #pragma unroll
            for (int j = 0; j < 8; ++j) ra[j] = 0.f;
        }
        const float4 w0 = *(const float4*)(W + (long)(k0 + bKh*8 + bKg)     * Ncol + nBase + bN);
        const float4 w1 = *(const float4*)(W + (long)(k0 + bKh*8 + bKg + 4) * Ncol + nBase + bN);
        rb[0]=w0.x; rb[1]=w0.y; rb[2]=w0.z; rb[3]=w0.w;
        rb[4]=w1.x; rb[5]=w1.y; rb[6]=w1.z; rb[7]=w1.w;
    };
    auto stageAB = [&](int buf) {
        uint2* Ap = AsI + buf*BUF_STR + aKh*KH_STR + aRow;
        #pragma unroll
        for (int j = 0; j < 4; ++j)
            Ap[j*KG_STR] = make_uint2(f2tf32(ra[j]), f2tf32(ra[j+4]));
        uint2* Bp = BsI + buf*BUF_STR + bKh*KH_STR + bKg*KG_STR + bN;
        #pragma unroll
        for (int j = 0; j < 4; ++j)
            Bp[j] = make_uint2(f2tf32(rb[j]), f2tf32(rb[j+4]));
    };

    float acc[2][8][4];
    #pragma unroll
    for (int mt = 0; mt < 2; ++mt)
        #pragma unroll
        for (int nt = 0; nt < 8; ++nt)
            #pragma unroll
            for (int i = 0; i < 4; ++i) acc[mt][nt][i] = 0.f;

    loadAB(0);
    stageAB(0);
    __syncthreads();
    int cur = 0;

    for (int k0 = 0; k0 < K; k0 += 16) {
        const bool more = (k0 + 16) < K;
        if (more) loadAB(k0 + 16);

        #pragma unroll
        for (int ks = 0; ks < 2; ++ks) {
            const uint2* Ab = AsI + cur*BUF_STR + ks*KH_STR + t4*KG_STR;
            uint2 a00 = Ab[wm + g];
            uint2 a01 = Ab[wm + g + 8];
            uint2 a10 = Ab[wm + 16 + g];
            uint2 a11 = Ab[wm + 16 + g + 8];
            const uint2* Bb = BsI + cur*BUF_STR + ks*KH_STR + t4*KG_STR + wn;
            #pragma unroll
            for (int nt = 0; nt < 8; ++nt) {
                uint2 bb = Bb[nt*8 + g];
                mma_tf32(acc[0][nt], a00.x, a01.x, a00.y, a01.y, bb.x, bb.y);
                mma_tf32(acc[1][nt], a10.x, a11.x, a10.y, a11.y, bb.x, bb.y);
            }
        }
        if (more) {
            stageAB(cur ^ 1);
            __syncthreads();
            cur ^= 1;
        }
    }

    // epilogue: scatter to (B,H,S,HD)
    #pragma unroll
    for (int mt = 0; mt < 2; ++mt) {
        int r0 = mBase + wm + mt * 16 + g;
        #pragma unroll
        for (int nt = 0; nt < 8; ++nt) {
            int c0 = nBase + wn + nt * 8 + 2 * t4;
            #pragma unroll
            for (int half = 0; half < 2; ++half) {
                int m = r0 + half * 8;
                if (m < NTOK) {
                    int b = m / NS, s = m % NS;
                    int hh0 = c0 >> 6, hd0 = c0 & 63;
                    float* cp = Cout + ((((long)b * NH + hh0) * NS + s) * HD + hd0);
                    cp[0] = acc[mt][nt][half*2 + 0] + bias[c0];
                    cp[1] = acc[mt][nt][half*2 + 1] + bias[c0 + 1];
                }
            }
        }
    }
}

// =====================================================================
// adv_finish: per (b,h): p2 (64), p1 (256), entropy, per-bh losses.
// =====================================================================
__global__ void adv_finish(const float* __restrict__ a2, const float* __restrict__ b2)
{
    __shared__ float sm_p2[64];
    __shared__ float sred1[8], sred2[8];
    const int bh = blockIdx.x;
    const int tid = threadIdx.x, lane = tid & 31, w = tid >> 5;

    float l2 = 0.f;
    if (tid < 64) {
        const float* pp = g_part2 + ((size_t)bh * 64 + tid) * 8;
        float s = b2[0];
        #pragma unroll
        for (int i = 0; i < 8; ++i) s += pp[i];
        float p = 1.f / (1.f + __expf(-s));
        sm_p2[tid] = p;
        l2 = __logf(fmaxf(1.f - p, EPSV));
    }
    float l1;
    float p1v;
    {
        const float* pp = g_part1 + ((size_t)bh * 256 + tid) * 8;
        float s = a2[0];
        #pragma unroll
        for (int i = 0; i < 8; ++i) s += pp[i];
        p1v = 1.f / (1.f + __expf(-s));
        l1 = __logf(fmaxf(1.f - p1v, EPSV));
    }
    #pragma unroll
    for (int o = 16; o > 0; o >>= 1) {
        l1 += __shfl_xor_sync(0xffffffffu, l1, o);
        l2 += __shfl_xor_sync(0xffffffffu, l2, o);
    }
    if (lane == 0) { sred1[w] = l1; sred2[w] = l2; }
    __syncthreads();

    {
        int t = tid;
        int gr = t >> 4, gc = t & 15;
        int m  = (gr >> 1) * 8 + (gc >> 1);
        float ad  = (1.f - LAMDA) * p1v + LAMDA * sm_p2[m];
        float ent = -ad * __log2f(ad + EPSV) - (1.f - ad) * __log2f(1.f - ad + EPSV);
        g_ent[bh * NS + 1 + t] = ent;
    }
    if (tid == 0) {
        g_ent[bh * NS] = 1.f;
        float s1 = 0.f, s2 = 0.f;
        #pragma unroll
        for (int i = 0; i < 8; ++i) { s1 += sred1[i]; s2 += sred2[i]; }
        g_loss1[bh] = s1;
        g_loss2[bh] = s2;
    }
}

// =====================================================================
// Tensor-core attention: one block per (b,h), 256 threads (8 warps).
// =====================================================================
#define KS_STRIDE 68
#define VT_STRIDE 268

__global__ void __launch_bounds__(256, 1)
attn_kernel()
{
    extern __shared__ unsigned smu[];
    unsigned* Ksm   = smu;                        // 264*68
    unsigned* VTu   = smu + 264*KS_STRIDE;        // 64*268
    float*    entS  = (float*)(VTu + 64*VT_STRIDE); // 264
    float*    sP    = entS + 264;                 // 264 (warp-7 scalar path)

    const int bh   = blockIdx.x;
    const int tid  = threadIdx.x;
    const int lane = tid & 31;
    const int w    = tid >> 5;
    const int g    = lane >> 2;
    const int t4   = lane & 3;

    const float* qb = g_qkv + (size_t)bh * NS * HD;
    const float* kb = g_qkv + (size_t)NQKV + (size_t)bh * NS * HD;
    const float* vb = g_qkv + (size_t)2*NQKV + (size_t)bh * NS * HD;

    for (int i = tid; i < NS*64; i += 256) {
        int t = i >> 6, d = i & 63;
        Ksm[t*KS_STRIDE + d] = f2tf32(kb[i]);
        VTu[d*VT_STRIDE + t] = f2tf32(vb[i]);
    }
    for (int i = tid; i < 7*64; i += 256) {
        int t = 257 + (i >> 6), d = i & 63;
        Ksm[t*KS_STRIDE + d] = 0u;
    }
    for (int i = tid; i < 64*8; i += 256) {
        int d = i >> 3, c = 256 + (i & 7);
        if (c >= 257) VTu[d*VT_STRIDE + c] = 0u;
    }
    for (int i = tid; i < 264; i += 256)
        entS[i] = (i < NS) ? g_ent[bh*NS + i] : 0.f;
    __syncthreads();

    const int b = bh / NH, h = bh % NH;
    const int qbase = lane & ~3;

    #pragma unroll
    for (int ti = 0; ti < 2; ++ti) {
        const int tile = w*2 + ti;
        const int m0   = tile * 16;

        unsigned aq[8][4];
        const float* q0 = qb + (m0 + g) * 64;
        const float* q1 = qb + (m0 + g + 8) * 64;
        #pragma unroll
        for (int ks = 0; ks < 8; ++ks) {
            aq[ks][0] = f2tf32(q0[ks*8 + t4]);
            aq[ks][1] = f2tf32(q1[ks*8 + t4]);
            aq[ks][2] = f2tf32(q0[ks*8 + t4 + 4]);
            aq[ks][3] = f2tf32(q1[ks*8 + t4 + 4]);
        }

        float sf[33][4];
        #pragma unroll
        for (int nt = 0; nt < 33; ++nt) {
            float c4[4] = {0.f, 0.f, 0.f, 0.f};
            const unsigned* kr = Ksm + (nt*8 + g) * KS_STRIDE;
            #pragma unroll
            for (int ks = 0; ks < 8; ++ks)
                mma_tf32(c4, aq[ks][0], aq[ks][1], aq[ks][2], aq[ks][3],
                         kr[ks*8 + t4], kr[ks*8 + t4 + 4]);
            sf[nt][0] = c4[0] * 0.125f;
            sf[nt][1] = c4[1] * 0.125f;
            sf[nt][2] = c4[2] * 0.125f;
            sf[nt][3] = c4[3] * 0.125f;
        }

        float mx0 = -1e30f, mx1 = -1e30f;
        #pragma unroll
        for (int nt = 0; nt < 32; ++nt) {
            mx0 = fmaxf(mx0, fmaxf(sf[nt][0], sf[nt][1]));
            mx1 = fmaxf(mx1, fmaxf(sf[nt][2], sf[nt][3]));
        }
        if (t4 == 0) {
            mx0 = fmaxf(mx0, sf[32][0]);
            mx1 = fmaxf(mx1, sf[32][2]);
        }
        mx0 = fmaxf(mx0, __shfl_xor_sync(0xffffffffu, mx0, 1));
        mx0 = fmaxf(mx0, __shfl_xor_sync(0xffffffffu, mx0, 2));
        mx1 = fmaxf(mx1, __shfl_xor_sync(0xffffffffu, mx1, 1));
        mx1 = fmaxf(mx1, __shfl_xor_sync(0xffffffffu, mx1, 2));

        float sum0 = 0.f, sum1 = 0.f;
        #pragma unroll
        for (int nt = 0; nt < 32; ++nt) {
            sf[nt][0] = __expf(sf[nt][0] - mx0); sum0 += sf[nt][0];
            sf[nt][1] = __expf(sf[nt][1] - mx0); sum0 += sf[nt][1];
            sf[nt][2] = __expf(sf[nt][2] - mx1); sum1 += sf[nt][2];
            sf[nt][3] = __expf(sf[nt][3] - mx1); sum1 += sf[nt][3];
        }
        {
            float e0 = (t4 == 0) ? __expf(sf[32][0] - mx0) : 0.f;
            float e2 = (t4 == 0) ? __expf(sf[32][2] - mx1) : 0.f;
            sf[32][0] = e0; sum0 += e0;
            sf[32][1] = 0.f;
            sf[32][2] = e2; sum1 += e2;
            sf[32][3] = 0.f;
        }
        sum0 += __shfl_xor_sync(0xffffffffu, sum0, 1);
        sum0 += __shfl_xor_sync(0xffffffffu, sum0, 2);
        sum1 += __shfl_xor_sync(0xffffffffu, sum1, 1);
        sum1 += __shfl_xor_sync(0xffffffffu, sum1, 2);
        const float inv0 = 1.f / sum0, inv1 = 1.f / sum1;

        const bool entRow = (tile == 0) && (g == 0);
        #pragma unroll
        for (int nt = 0; nt < 33; ++nt) {
            sf[nt][0] *= inv0;
            sf[nt][1] *= inv0;
            sf[nt][2] *= inv1;
            sf[nt][3] *= inv1;
            if (entRow) {
                sf[nt][0] *= entS[nt*8 + 2*t4];
                sf[nt][1] *= entS[nt*8 + 2*t4 + 1];
            }
        }

        float oc[8][4];
        #pragma unroll
        for (int nt = 0; nt < 8; ++nt)
            #pragma unroll
            for (int i = 0; i < 4; ++i) oc[nt][i] = 0.f;

        const int l1 = qbase + (t4 >> 1);
        const int l2 = l1 + 2;
        const bool odd = (t4 & 1);

        #pragma unroll
        for (int ks = 0; ks < 33; ++ks) {
            unsigned u0 = f2tf32(sf[ks][0]);
            unsigned u1 = f2tf32(sf[ks][1]);
            unsigned u2 = f2tf32(sf[ks][2]);
            unsigned u3 = f2tf32(sf[ks][3]);
            unsigned x0a = __shfl_sync(0xffffffffu, u0, l1);
            unsigned x0b = __shfl_sync(0xffffffffu, u1, l1);
            unsigned x1a = __shfl_sync(0xffffffffu, u2, l1);
            unsigned x1b = __shfl_sync(0xffffffffu, u3, l1);
            unsigned y0a = __shfl_sync(0xffffffffu, u0, l2);
            unsigned y0b = __shfl_sync(0xffffffffu, u1, l2);
            unsigned y1a = __shfl_sync(0xffffffffu, u2, l2);
            unsigned y1b = __shfl_sync(0xffffffffu, u3, l2);
            unsigned a0 = odd ? x0b : x0a;
            unsigned a1 = odd ? x1b : x1a;
            unsigned a2 = odd ? y0b : y0a;
            unsigned a3 = odd ? y1b : y1a;
            #pragma unroll
            for (int nt = 0; nt < 8; ++nt) {
                const unsigned* vr = VTu + (nt*8 + g) * VT_STRIDE + ks*8;
                mma_tf32(oc[nt], a0, a1, a2, a3, vr[t4], vr[t4 + 4]);
            }
        }

        float* base0 = g_ctx + ((size_t)(b*NS + m0 + g    )) * ND + h*HD;
        float* base1 = g_ctx + ((size_t)(b*NS + m0 + g + 8)) * ND + h*HD;
        #pragma unroll
        for (int nt = 0; nt < 8; ++nt) {
            int c0 = nt*8 + 2*t4;
            base0[c0]     = oc[nt][0];
            base0[c0 + 1] = oc[nt][1];
            base1[c0]     = oc[nt][2];
            base1[c0 + 1] = oc[nt][3];
        }
    }

    // ---- query 256: scalar path on warp 7
    if (w == 7) {
        float q[64];
        #pragma unroll
        for (int d = 0; d < 64; ++d) q[d] = qb[256*64 + d];

        float sc[9];
        #pragma unroll
        for (int c = 0; c < 9; ++c) {
            int kt = lane + 32*c;
            float acc = -1e30f;
            if (kt <= 256) {
                acc = 0.f;
                const unsigned* kr = Ksm + kt * KS_STRIDE;
                #pragma unroll
                for (int d = 0; d < 64; ++d)
                    acc = fmaf(q[d], __uint_as_float(kr[d]), acc);
                acc *= 0.125f;
            }
            sc[c] = acc;
        }
        float mx = sc[0];
        #pragma unroll
        for (int c = 1; c < 9; ++c) mx = fmaxf(mx, sc[c]);
        #pragma unroll
        for (int o = 16; o > 0; o >>= 1) mx = fmaxf(mx, __shfl_xor_sync(0xffffffffu, mx, o));
        float sum = 0.f;
        #pragma unroll
        for (int c = 0; c < 9; ++c) {
            int kt = lane + 32*c;
            float e = (kt <= 256) ? __expf(sc[c] - mx) : 0.f;
            sc[c] = e; sum += e;
        }
        #pragma unroll
        for (int o = 16; o > 0; o >>= 1) sum += __shfl_xor_sync(0xffffffffu, sum, o);
        float inv = 1.f / sum;
        #pragma unroll
        for (int c = 0; c < 9; ++c) {
            int kt = lane + 32*c;
            if (kt <= 256) sP[kt] = sc[c] * inv;
        }
        __syncwarp();

        float a0 = 0.f, a1 = 0.f;
        const unsigned* v0 = VTu + (size_t)lane * VT_STRIDE;
        const unsigned* v1 = VTu + (size_t)(lane + 32) * VT_STRIDE;
        for (int t = 0; t < NS; ++t) {
            float pv = sP[t];
            a0 = fmaf(pv, __uint_as_float(v0[t]), a0);
            a1 = fmaf(pv, __uint_as_float(v1[t]), a1);
        }
        float* cp = g_ctx + ((size_t)(b*NS + 256)) * ND + h*HD;
        cp[lane]      = a0;
        cp[lane + 32] = a1;
    }
}

// =====================================================================
// Final deterministic loss reduction
// =====================================================================
__global__ void loss_kernel(float* __restrict__ out)
{
    __shared__ float s1[256], s2[256];
    int tid = threadIdx.x;
    float a = 0.f, b = 0.f;
    for (int i = tid; i < NBH; i += 256) { a += g_loss1[i]; b += g_loss2[i]; }
    s1[tid] = a; s2[tid] = b;
    __syncthreads();
    for (int o = 128; o > 0; o >>= 1) {
        if (tid < o) { s1[tid] += s1[tid + o]; s2[tid] += s2[tid + o]; }
        __syncthreads();
    }
    if (tid == 0)
        out[0] = -s1[0] / ((float)NBH * 256.f) - s2[0] / ((float)NBH * 64.f);
}

// =====================================================================
// Launch
// =====================================================================
extern "C" void kernel_launch(void* const* d_in, const int* in_sizes, int n_in,
                              void* d_out, int out_size)
{
    const float* X  = (const float*)d_in[0];
    const float* Wq = (const float*)d_in[1];
    const float* bq = (const float*)d_in[2];
    const float* Wk = (const float*)d_in[3];
    const float* bk = (const float*)d_in[4];
    const float* Wv = (const float*)d_in[5];
    const float* bv = (const float*)d_in[6];
    const float* Wo = (const float*)d_in[7];
    const float* bo = (const float*)d_in[8];
    const float* A1 = (const float*)d_in[9];
    const float* a1 = (const float*)d_in[10];
    const float* A2 = (const float*)d_in[11];
    const float* a2 = (const float*)d_in[12];
    const float* B1 = (const float*)d_in[13];
    const float* b1 = (const float*)d_in[14];
    const float* B2 = (const float*)d_in[15];
    const float* b2 = (const float*)d_in[16];
    float* out = (float*)d_out;

    float *qkv = nullptr, *ctx = nullptr, *pt1 = nullptr, *pt2 = nullptr;
    cudaGetSymbolAddress((void**)&qkv, g_qkv);
    cudaGetSymbolAddress((void**)&ctx, g_ctx);
    cudaGetSymbolAddress((void**)&pt1, g_part1);
    cudaGetSymbolAddress((void**)&pt2, g_part2);
    float* kbase = qkv + NQKV;

    const int ATTN_SMEM = (264*KS_STRIDE + 64*VT_STRIDE + 264 + 264) * 4; // 142528
    cudaFuncSetAttribute(attn_kernel, cudaFuncAttributeMaxDynamicSharedMemorySize, ATTN_SMEM);

    // fused QKV projection
    gemm_qkv<<<dim3(18, (NTOK + 127)/128), 256>>>(X, Wq, bq, Wk, bk, Wv, bv);

    // adversarial layer-1 GEMMs with fused relu+layer-2 partial dot
    gemm_tc<2,3><<<dim3(4, (NBH*256)/128), 256>>>(kbase, A1, a1, A2, pt1, NBH*256, 512, 64);
    gemm_tc<3,3><<<dim3(4, (NBH*64)/128),  256>>>(kbase, B1, b1, B2, pt2, NBH*64,  512, 256);

    adv_finish<<<NBH, 256>>>(a2, b2);

    attn_kernel<<<NBH, 256, ATTN_SMEM>>>();

    gemm_tc<0,0><<<dim3(6, (NTOK + 127)/128), 256>>>(ctx, Wo, bo, nullptr, out, NTOK, ND, ND);

    if (out_size > NQKV)
        loss_kernel<<<1, 256>>>(out + (out_size - 1));
}